// round 14
// baseline (speedup 1.0000x reference)
#include <cuda_runtime.h>
#include <cstdint>
#include <math.h>

// Problem constants
#define S_TOK 8192
#define MDIM  4096
#define NEXP  64
#define CAP   128
#define SEC   67108864ULL            // S*E*C
#define OUT_FLOATS 134217793ULL      // 1 + 2*SEC + 64
#define ZMAIN 134217728ULL           // floats zeroed by bulk path (512MB)

// GEMM tiling (packed-K formulation)
#define TILE_M 256                   // tokens per CTA
#define KB     8                     // k per step (2 quads)
#define KSPLIT 4
#define KCHUNK (MDIM / KSPLIT)       // 1024
#define NSTEP  (KCHUNK / KB)         // 128
#define NTB    (S_TOK / TILE_M)      // 32 token blocks
#define GRID_G (NTB * KSPLIT)        // 128 CTAs (1 per SM)
#define CTHR   256                   // compute threads (8 warps)
#define THREADS (CTHR + 32)          // + 1 TMA-zero warp
#define LDR    12                    // padded row stride (floats): 48B, conflict-free

#define ZCHUNK 4096                  // bytes per bulk store
#define ZPC    1024                  // chunks per CTA (128*1024*4KB = 512MB)

#define NBLK64 (S_TOK / 64)          // 128 blocks for gate/scatter

typedef unsigned long long u64;
typedef unsigned int u32;

// ---------- scratch (device globals; fully overwritten each launch) ----------
__device__ float g_part[KSPLIT * S_TOK * NEXP];   // 8 MB partial logits
__device__ int   g_eid[S_TOK];
__device__ float g_gate[S_TOK];
__device__ float g_me[NBLK64 * NEXP];
__device__ int   g_cnt[NBLK64 * NEXP];

// packed f32x2 FMA (PTX-only; ptxas never auto-fuses)
__device__ __forceinline__ void ffma2(u64& d, u64 a, u64 b) {
    asm("fma.rn.f32x2 %0, %1, %2, %0;" : "+l"(d) : "l"(a), "l"(b));
}
__device__ __forceinline__ void barc() {   // compute-warps-only barrier
    asm volatile("bar.sync 1, %0;" :: "n"(CTHR) : "memory");
}
__device__ __forceinline__ u32 smem_u32(const void* p) {
    u32 a;
    asm("{ .reg .u64 t; cvta.to.shared.u64 t, %1; cvt.u32.u64 %0, t; }"
        : "=r"(a) : "l"(p));
    return a;
}
__device__ __forceinline__ void cpa16(u32 dst, const float* src) {
    asm volatile("cp.async.cg.shared.global [%0], [%1], 16;"
                 :: "r"(dst), "l"(src) : "memory");
}

// ---------------------------------------------------------------------------
// Kernel 1: warps 0-7 = 256x64 fp32 GEMM over a K/4 chunk, packed-K FFMA2:
// acc[tok][exp] f32x2 accumulates two k-lanes; A/B in natural [row][k] smem
// staged by cp.async (no transpose, no dup2, no STS in compute stream).
// Warp 8 = TMA bulk-zero of the 537MB output (R9 proven engine).
// ---------------------------------------------------------------------------
__global__ __launch_bounds__(THREADS, 1) void gemm_zero_kernel(
    const float* __restrict__ x, const float* __restrict__ wg,
    float* __restrict__ out)
{
    __shared__ float sA[2][TILE_M * LDR];             // 2 x 12 KB
    __shared__ float sB[2][NEXP * LDR];               // 2 x 3 KB
    __shared__ alignas(16) float4 zbuf[ZCHUNK / 16];  // 4 KB zeros

    const int t  = threadIdx.x;
    const int bx = blockIdx.x;

    {
        const float4 z = make_float4(0.f, 0.f, 0.f, 0.f);
        for (int i = t; i < ZCHUNK / 16; i += THREADS) zbuf[i] = z;
    }
    __syncthreads();

    if (t >= CTHR) {
        // ---------------- TMA zero warp ----------------
        const int zt = t - CTHR;
        if (zt == 0) {
            asm volatile("fence.proxy.async.shared::cta;" ::: "memory");
            const u32 zaddr = smem_u32(zbuf);
            char* dst = (char*)out + (size_t)bx * (ZPC * (size_t)ZCHUNK);
            #pragma unroll 4
            for (int c = 0; c < ZPC; c++) {
                asm volatile(
                    "cp.async.bulk.global.shared::cta.bulk_group [%0], [%1], %2;"
                    :: "l"(dst + (size_t)c * ZCHUNK), "r"(zaddr), "r"(ZCHUNK)
                    : "memory");
            }
            asm volatile("cp.async.bulk.commit_group;" ::: "memory");
            asm volatile("cp.async.bulk.wait_group 0;" ::: "memory");
        }
        if (bx == 0) {   // tail: last 65 floats
            for (int i = zt; i < (int)(OUT_FLOATS - ZMAIN); i += 32)
                out[ZMAIN + i] = 0.0f;
        }
        return;
    }

    // ---------------- compute warps ----------------
    const int tb = bx & (NTB - 1);     // token block (0..31)
    const int kh = bx >> 5;            // k chunk (0..3)
    const int w    = t >> 5;           // warp 0..7
    const int lane = t & 31;
    const int tb2  = w >> 1;           // warp token sub-block (0..3): 64 tokens
    const int eb   = w & 1;            // warp expert half (0..1): 32 experts
    const int tg   = lane >> 2;        // lane token offset (0..7)
    const int eg   = lane & 3;         // lane expert offset (0..3)
    // thread owns tokens  tb2*64 + tg + 8*ti (ti=0..7)
    //            experts  eb*32  + eg + 4*ei (ei=0..7)

    u64 acc[8][8];                     // [token][expert] packed k-lanes
    #pragma unroll
    for (int i = 0; i < 8; i++)
        #pragma unroll
        for (int j = 0; j < 8; j++) acc[i][j] = 0ULL;

    const float* xblk = x  + (size_t)tb * TILE_M * MDIM + (size_t)kh * KCHUNK;
    const float* wblk = wg + (size_t)kh * KCHUNK;

    // staging addresses (cp.async, 16B chunks)
    // A: thread t copies row t, halves 0..1 (KB=8 floats = 32B per row)
    // B: threads 0..127 copy row t>>1, half t&1
    const u32 saA[2] = { smem_u32(&sA[0][0]), smem_u32(&sA[1][0]) };
    const u32 saB[2] = { smem_u32(&sB[0][0]), smem_u32(&sB[1][0]) };
    const u32 adst0 = (u32)t * (LDR * 4);
    const u32 bdst0 = (u32)(t >> 1) * (LDR * 4) + (u32)(t & 1) * 16;

    // prologue: stage step 0
    {
        const float* asrc = xblk + (size_t)t * MDIM;
        cpa16(saA[0] + adst0,      asrc);
        cpa16(saA[0] + adst0 + 16, asrc + 4);
        if (t < 128)
            cpa16(saB[0] + bdst0, wblk + (size_t)(t >> 1) * MDIM + (t & 1) * 4);
        asm volatile("cp.async.commit_group;" ::: "memory");
        asm volatile("cp.async.wait_group 0;" ::: "memory");
    }
    barc();

    // compute-lane smem byte offsets (within a buffer)
    const u32 aoff = (u32)(tb2 * 64 + tg) * (LDR * 4);   // + ti*8*LDR*4 + q*16
    const u32 boff = (u32)(eb * 32 + eg) * (LDR * 4);    // + ei*4*LDR*4 + q*16

    #pragma unroll 1
    for (int s = 0; s < NSTEP; s++) {
        const int cur = s & 1;

        if (s + 1 < NSTEP) {           // stage next step (async)
            const int k1 = (s + 1) * KB;
            const int nxt = cur ^ 1;
            const float* asrc = xblk + (size_t)t * MDIM + k1;
            cpa16(saA[nxt] + adst0,      asrc);
            cpa16(saA[nxt] + adst0 + 16, asrc + 4);
            if (t < 128)
                cpa16(saB[nxt] + bdst0, wblk + (size_t)(t >> 1) * MDIM + k1 + (t & 1) * 4);
            asm volatile("cp.async.commit_group;" ::: "memory");
        }

        // compute: 2 quads x (8 aLDS + 8 bLDS + 128 FFMA2)
        const char* Abase = (const char*)&sA[cur][0] + aoff;
        const char* Bbase = (const char*)&sB[cur][0] + boff;
        #pragma unroll
        for (int q = 0; q < 2; q++) {
            ulonglong2 bv[8];
            #pragma unroll
            for (int e = 0; e < 8; e++)
                bv[e] = *(const ulonglong2*)(Bbase + e * (4 * LDR * 4) + q * 16);
            #pragma unroll
            for (int ti = 0; ti < 8; ti++) {
                ulonglong2 av = *(const ulonglong2*)(Abase + ti * (8 * LDR * 4) + q * 16);
                #pragma unroll
                for (int e = 0; e < 8; e++) {
                    ffma2(acc[ti][e], av.x, bv[e].x);
                    ffma2(acc[ti][e], av.y, bv[e].y);
                }
            }
        }

        if (s + 1 < NSTEP) {
            asm volatile("cp.async.wait_group 0;" ::: "memory");
            barc();
        }
    }

    // epilogue: logit = lo + hi; write partial logits [kh][token][expert]
    float* part = g_part + (size_t)kh * S_TOK * NEXP;
    const int tokbase = tb * TILE_M + tb2 * 64 + tg;
    const int ebase   = eb * 32 + eg;
    #pragma unroll
    for (int ti = 0; ti < 8; ti++) {
        const size_t row = (size_t)(tokbase + ti * 8) * NEXP;
        #pragma unroll
        for (int e = 0; e < 8; e++) {
            float lo = __uint_as_float((unsigned)acc[ti][e]);
            float hi = __uint_as_float((unsigned)(acc[ti][e] >> 32));
            part[row + ebase + e * 4] = lo + hi;
        }
    }
}

// ---------------------------------------------------------------------------
// Kernel 2 (R6): reduce K-split partials, softmax/argmax, per-block me/cnt.
// ---------------------------------------------------------------------------
__global__ __launch_bounds__(256) void gate_kernel()
{
    __shared__ float Ls[64 * 65];
    __shared__ int   s_eid[64];
    const int b = blockIdx.x;        // 0..127
    const int t = threadIdx.x;
    const size_t off = (size_t)b * 64 * NEXP;

    #pragma unroll
    for (int i = 0; i < 4; i++) {
        const int idx4 = t + i * 256;     // 0..1023
        float4 v = *(const float4*)&g_part[off + (size_t)idx4 * 4];
        #pragma unroll
        for (int p = 1; p < KSPLIT; p++) {
            float4 w = *(const float4*)&g_part[(size_t)p * S_TOK * NEXP + off + (size_t)idx4 * 4];
            v.x += w.x; v.y += w.y; v.z += w.z; v.w += w.w;
        }
        const int r = (idx4 * 4) >> 6;
        const int e = (idx4 * 4) & 63;
        Ls[r * 65 + e + 0] = v.x;
        Ls[r * 65 + e + 1] = v.y;
        Ls[r * 65 + e + 2] = v.z;
        Ls[r * 65 + e + 3] = v.w;
    }
    __syncthreads();

    if (t < 64) {
        const int r = t;
        float m = -INFINITY; int am = 0;
        #pragma unroll 8
        for (int e = 0; e < NEXP; e++) {
            float v = Ls[r * 65 + e];
            if (v > m) { m = v; am = e; }
        }
        float sum = 0.f;
        #pragma unroll 8
        for (int e = 0; e < NEXP; e++) {
            float ex = expf(Ls[r * 65 + e] - m);
            Ls[r * 65 + e] = ex;
            sum += ex;
        }
        const float inv = 1.f / sum;
        #pragma unroll 8
        for (int e = 0; e < NEXP; e++) Ls[r * 65 + e] *= inv;
        const int s = b * 64 + r;
        g_eid[s]  = am;
        g_gate[s] = inv;
        s_eid[r]  = am;
    }
    __syncthreads();

    if (t < NEXP) {
        const int e = t;
        float msum = 0.f; int cnt = 0;
        #pragma unroll 8
        for (int r = 0; r < 64; r++) {
            msum += Ls[r * 65 + e];
            cnt  += (s_eid[r] == e);
        }
        g_me[b * NEXP + e]  = msum;
        g_cnt[b * NEXP + e] = cnt;
    }
}

// ---------------------------------------------------------------------------
// Kernel 3 (R9/R12 proven): scatter + exp_counts + l_aux.
// ---------------------------------------------------------------------------
__global__ __launch_bounds__(256) void scatter_kernel(float* __restrict__ out)
{
    __shared__ int   sc[NBLK64 * NEXP];   // 32 KB staged counts
    __shared__ int   s_part[4][64];
    __shared__ int   s_e[64];
    __shared__ float s_g[64];
    __shared__ int   cnt0[NEXP];
    __shared__ float s_val[NEXP];

    const int b = blockIdx.x;
    const int t = threadIdx.x;            // 0..255

    {
        const int4* g4 = (const int4*)g_cnt;
        int4* s4 = (int4*)sc;
        #pragma unroll
        for (int j = 0; j < 8; j++) s4[t + j * 256] = g4[t + j * 256];
    }
    if (t < 64) {
        s_e[t]  = g_eid[b * 64 + t];
        s_g[t]  = g_gate[b * 64 + t];
        cnt0[t] = 0;
    }
    __syncthreads();

    {
        const int tok = t & 63;
        const int q   = t >> 6;
        const int e   = s_e[tok];
        const int lo  = q * 32;
        const int hi  = (b < lo + 32) ? b : (lo + 32);
        int sum = 0;
        #pragma unroll 8
        for (int bp = lo; bp < hi; bp++) sum += sc[bp * NEXP + e];
        s_part[q][tok] = sum;
    }
    __syncthreads();

    int ee = 0, rank_w = 0, offs = 0; float gg = 0.f; unsigned mm = 0;
    if (t < 64) {
        ee   = s_e[t];
        gg   = s_g[t];
        offs = s_part[0][t] + s_part[1][t] + s_part[2][t] + s_part[3][t];
        mm   = __match_any_sync(0xFFFFFFFFu, ee);
        const int lane = t & 31;
        rank_w = __popc(mm & ((1u << lane) - 1u));
        if (t < 32 && lane == __ffs(mm) - 1) cnt0[ee] = __popc(mm);
    }
    __syncthreads();
    if (t >= 32 && t < 64) rank_w += cnt0[ee];
    if (t < 64) {
        const int rank = offs + rank_w;
        if (rank < CAP) {
            const int s = b * 64 + t;
            size_t base = (size_t)s * (NEXP * CAP) + (size_t)ee * CAP + rank;
            out[1 + base]       = gg;
            out[1 + SEC + base] = 1.0f;
        }
    }

    if (b == 0) {
        __syncthreads();
        {
            const int ex = t & 63;
            const int q  = t >> 6;
            int sum = 0;
            #pragma unroll 8
            for (int bp = q * 32; bp < q * 32 + 32; bp++) sum += sc[bp * NEXP + ex];
            s_part[q][ex] = sum;
        }
        __syncthreads();
        if (t < 64) {
            const int run = s_part[0][t] + s_part[1][t] + s_part[2][t] + s_part[3][t];
            float me_tot = 0.f;
            #pragma unroll 8
            for (int bp = 0; bp < NBLK64; bp++) me_tot += g_me[bp * NEXP + t];
            out[1 + 2 * SEC + t] = (float)run;
            s_val[t] = me_tot * (float)run;
        }
        __syncthreads();
        if (t == 0) {
            float acc = 0.f;
            for (int k = 0; k < NEXP; k++) acc += s_val[k];
            out[0] = acc * (1.f / 1048576.f);
        }
    }
}

// ---------------------------------------------------------------------------
extern "C" void kernel_launch(void* const* d_in, const int* in_sizes, int n_in,
                              void* d_out, int out_size)
{
    const float* x  = (const float*)d_in[0];
    const float* wg = (const float*)d_in[1];
    float* out = (float*)d_out;

    gemm_zero_kernel<<<GRID_G, THREADS>>>(x, wg, out);
    gate_kernel<<<NBLK64, 256>>>();
    scatter_kernel<<<NBLK64, 256>>>(out);
}

// round 15
// speedup vs baseline: 1.4200x; 1.4200x over previous
#include <cuda_runtime.h>
#include <cstdint>
#include <math.h>

// Problem constants
#define S_TOK 8192
#define MDIM  4096
#define NEXP  64
#define CAP   128
#define SEC   67108864ULL            // S*E*C
#define OUT_FLOATS 134217793ULL      // 1 + 2*SEC + 64
#define ZMAIN 134217728ULL           // floats zeroed by bulk path (512MB)

// GEMM tiling: R6 layout, 16 compute warps, 4tok x 8exp per thread
#define TILE_M 256                   // tokens per CTA
#define KB     16
#define KSPLIT 4
#define KCHUNK (MDIM / KSPLIT)       // 1024
#define NSTEP  (KCHUNK / KB)         // 64
#define NTB    (S_TOK / TILE_M)      // 32 token blocks
#define GRID_G (NTB * KSPLIT)        // 128 CTAs (1 per SM)
#define CTHR   512                   // compute threads (16 warps)
#define THREADS (CTHR + 32)          // + 1 TMA-zero warp
#define LDA 260                      // A smem row stride (floats)
#define LDB 68                       // B smem row stride (floats)

#define ZCHUNK 4096                  // bytes per bulk store
#define ZPC    1024                  // chunks per CTA (128*1024*4KB = 512MB)

#define NBLK64 (S_TOK / 64)          // 128 blocks for gate/scatter

typedef unsigned long long u64;
typedef unsigned int u32;

// ---------- scratch (device globals; fully overwritten each launch) ----------
__device__ float g_part[KSPLIT * S_TOK * NEXP];   // 8 MB partial logits
__device__ int   g_eid[S_TOK];
__device__ float g_gate[S_TOK];
__device__ float g_me[NBLK64 * NEXP];
__device__ int   g_cnt[NBLK64 * NEXP];

// packed f32x2 FMA (PTX-only; ptxas never auto-fuses)
__device__ __forceinline__ void ffma2(u64& d, u64 a, u64 b) {
    asm("fma.rn.f32x2 %0, %1, %2, %0;" : "+l"(d) : "l"(a), "l"(b));
}
__device__ __forceinline__ u64 dup2(float b) {
    u64 r; unsigned u = __float_as_uint(b);
    asm("mov.b64 %0, {%1, %1};" : "=l"(r) : "r"(u));
    return r;
}
__device__ __forceinline__ void barc() {   // compute-warps-only barrier
    asm volatile("bar.sync 1, %0;" :: "n"(CTHR) : "memory");
}
__device__ __forceinline__ u32 smem_u32(const void* p) {
    u32 a;
    asm("{ .reg .u64 t; cvta.to.shared.u64 t, %1; cvt.u32.u64 %0, t; }"
        : "=r"(a) : "l"(p));
    return a;
}

// ---------------------------------------------------------------------------
// Kernel 1: warps 0-15 = 256x64 fp32 GEMM over a K/4 chunk. R6 smem layout
// (A transposed [k][row], B [k][e]); per-thread tile 4 tok x 8 exp =
// 16 FFMA2 / 3 single-wavefront LDS.128 / 8 dup2(alu) per kk. 4 warps/SMSP
// saturate the fma pipe. Warp 16 = TMA bulk-zero (R9 proven engine).
// ---------------------------------------------------------------------------
__global__ __launch_bounds__(THREADS, 1) void gemm_zero_kernel(
    const float* __restrict__ x, const float* __restrict__ wg,
    float* __restrict__ out)
{
    __shared__ float sA[2][KB * LDA];                 // 2 x 16.25 KB
    __shared__ float sB[2][KB * LDB];                 // 2 x 4.25 KB
    __shared__ alignas(16) float4 zbuf[ZCHUNK / 16];  // 4 KB zeros

    const int t  = threadIdx.x;
    const int bx = blockIdx.x;

    {
        const float4 z = make_float4(0.f, 0.f, 0.f, 0.f);
        for (int i = t; i < ZCHUNK / 16; i += THREADS) zbuf[i] = z;
    }
    __syncthreads();

    if (t >= CTHR) {
        // ---------------- TMA zero warp ----------------
        const int zt = t - CTHR;
        if (zt == 0) {
            asm volatile("fence.proxy.async.shared::cta;" ::: "memory");
            const u32 zaddr = smem_u32(zbuf);
            char* dst = (char*)out + (size_t)bx * (ZPC * (size_t)ZCHUNK);
            #pragma unroll 4
            for (int c = 0; c < ZPC; c++) {
                asm volatile(
                    "cp.async.bulk.global.shared::cta.bulk_group [%0], [%1], %2;"
                    :: "l"(dst + (size_t)c * ZCHUNK), "r"(zaddr), "r"(ZCHUNK)
                    : "memory");
            }
            asm volatile("cp.async.bulk.commit_group;" ::: "memory");
            asm volatile("cp.async.bulk.wait_group 0;" ::: "memory");
        }
        if (bx == 0) {   // tail: last 65 floats
            for (int i = zt; i < (int)(OUT_FLOATS - ZMAIN); i += 32)
                out[ZMAIN + i] = 0.0f;
        }
        return;
    }

    // ---------------- compute warps ----------------
    const int tb = bx & (NTB - 1);     // token block (0..31)
    const int kh = bx >> 5;            // k chunk (0..3)
    const int w    = t >> 5;           // warp 0..15
    const int lane = t & 31;
    const int ts   = w >> 1;           // warp token sub-block (0..7): 32 tokens
    const int eb   = w & 1;            // warp expert half (0..1): 32 experts
    const int tg   = lane >> 2;        // token group (0..7): 4 tokens
    const int eg   = lane & 3;         // expert group (0..3): 8 experts
    const int tok0 = ts * 32 + tg * 4;
    const int e0   = eb * 32 + eg * 8;

    u64 acc[2][8];                     // 2 token-pairs x 8 experts (32 regs)
    #pragma unroll
    for (int p = 0; p < 2; p++)
        #pragma unroll
        for (int j = 0; j < 8; j++) acc[p][j] = 0ULL;

    const float* xblk = x  + (size_t)tb * TILE_M * MDIM + (size_t)kh * KCHUNK;
    const float* wblk = wg + (size_t)kh * KCHUNK;

    // staging: A = 2 float4/thread (row t>>1, cols (t&1)*8 + {0,4})
    //          B = 1 float4 by threads 0..255 (row t>>2, cols (t&3)*4)
    const int arow = t >> 1;           // 0..255
    const int ac0  = (t & 1) * 8;      // 0 or 8
    const int brow = t >> 2;           // 0..63 (expert, threads < 256)
    const int bkq  = t & 3;            // 0..3

    float4 pa0, pa1, pb;
    pa0 = *(const float4*)(xblk + (size_t)arow * MDIM + ac0);
    pa1 = *(const float4*)(xblk + (size_t)arow * MDIM + ac0 + 4);
    if (t < 256) pb = *(const float4*)(wblk + (size_t)brow * MDIM + bkq * 4);

    // stage step 0
    sA[0][(ac0 + 0) * LDA + arow] = pa0.x;
    sA[0][(ac0 + 1) * LDA + arow] = pa0.y;
    sA[0][(ac0 + 2) * LDA + arow] = pa0.z;
    sA[0][(ac0 + 3) * LDA + arow] = pa0.w;
    sA[0][(ac0 + 4) * LDA + arow] = pa1.x;
    sA[0][(ac0 + 5) * LDA + arow] = pa1.y;
    sA[0][(ac0 + 6) * LDA + arow] = pa1.z;
    sA[0][(ac0 + 7) * LDA + arow] = pa1.w;
    if (t < 256) {
        sB[0][(bkq * 4 + 0) * LDB + brow] = pb.x;
        sB[0][(bkq * 4 + 1) * LDB + brow] = pb.y;
        sB[0][(bkq * 4 + 2) * LDB + brow] = pb.z;
        sB[0][(bkq * 4 + 3) * LDB + brow] = pb.w;
    }
    barc();

    #pragma unroll 1
    for (int s = 0; s < NSTEP; s++) {
        const int cur = s & 1;

        if (s + 1 < NSTEP) {           // prefetch next step
            const int k1 = (s + 1) * KB;
            pa0 = *(const float4*)(xblk + (size_t)arow * MDIM + k1 + ac0);
            pa1 = *(const float4*)(xblk + (size_t)arow * MDIM + k1 + ac0 + 4);
            if (t < 256)
                pb = *(const float4*)(wblk + (size_t)brow * MDIM + k1 + bkq * 4);
        }

        // inner loop: 3 LDS.128 + 8 dup2(alu) + 16 FFMA2 per kk
        #pragma unroll
        for (int kk = 0; kk < KB; kk++) {
            ulonglong2 ap = *(const ulonglong2*)&sA[cur][kk * LDA + tok0];
            float4 b03 = *(const float4*)&sB[cur][kk * LDB + e0];
            float4 b47 = *(const float4*)&sB[cur][kk * LDB + e0 + 4];
            u64 ar[2] = { ap.x, ap.y };
            u64 bd[8] = { dup2(b03.x), dup2(b03.y), dup2(b03.z), dup2(b03.w),
                          dup2(b47.x), dup2(b47.y), dup2(b47.z), dup2(b47.w) };
            #pragma unroll
            for (int p = 0; p < 2; p++)
                #pragma unroll
                for (int j = 0; j < 8; j++)
                    ffma2(acc[p][j], ar[p], bd[j]);
        }

        if (s + 1 < NSTEP) {           // stage next step into other buffer
            const int nxt = cur ^ 1;
            sA[nxt][(ac0 + 0) * LDA + arow] = pa0.x;
            sA[nxt][(ac0 + 1) * LDA + arow] = pa0.y;
            sA[nxt][(ac0 + 2) * LDA + arow] = pa0.z;
            sA[nxt][(ac0 + 3) * LDA + arow] = pa0.w;
            sA[nxt][(ac0 + 4) * LDA + arow] = pa1.x;
            sA[nxt][(ac0 + 5) * LDA + arow] = pa1.y;
            sA[nxt][(ac0 + 6) * LDA + arow] = pa1.z;
            sA[nxt][(ac0 + 7) * LDA + arow] = pa1.w;
            if (t < 256) {
                sB[nxt][(bkq * 4 + 0) * LDB + brow] = pb.x;
                sB[nxt][(bkq * 4 + 1) * LDB + brow] = pb.y;
                sB[nxt][(bkq * 4 + 2) * LDB + brow] = pb.z;
                sB[nxt][(bkq * 4 + 3) * LDB + brow] = pb.w;
            }
        }
        barc();
    }

    // epilogue: write partial logits [kh][token][expert]
    float* part = g_part + (size_t)kh * S_TOK * NEXP;
    #pragma unroll
    for (int p = 0; p < 2; p++) {
        const size_t t0 = (size_t)tb * TILE_M + tok0 + p * 2;
        float4 lo0, lo1, hi0, hi1;
        lo0.x = __uint_as_float((unsigned)acc[p][0]);
        lo0.y = __uint_as_float((unsigned)acc[p][1]);
        lo0.z = __uint_as_float((unsigned)acc[p][2]);
        lo0.w = __uint_as_float((unsigned)acc[p][3]);
        lo1.x = __uint_as_float((unsigned)acc[p][4]);
        lo1.y = __uint_as_float((unsigned)acc[p][5]);
        lo1.z = __uint_as_float((unsigned)acc[p][6]);
        lo1.w = __uint_as_float((unsigned)acc[p][7]);
        hi0.x = __uint_as_float((unsigned)(acc[p][0] >> 32));
        hi0.y = __uint_as_float((unsigned)(acc[p][1] >> 32));
        hi0.z = __uint_as_float((unsigned)(acc[p][2] >> 32));
        hi0.w = __uint_as_float((unsigned)(acc[p][3] >> 32));
        hi1.x = __uint_as_float((unsigned)(acc[p][4] >> 32));
        hi1.y = __uint_as_float((unsigned)(acc[p][5] >> 32));
        hi1.z = __uint_as_float((unsigned)(acc[p][6] >> 32));
        hi1.w = __uint_as_float((unsigned)(acc[p][7] >> 32));
        *(float4*)&part[t0 * NEXP + e0 + 0]       = lo0;
        *(float4*)&part[t0 * NEXP + e0 + 4]       = lo1;
        *(float4*)&part[(t0 + 1) * NEXP + e0 + 0] = hi0;
        *(float4*)&part[(t0 + 1) * NEXP + e0 + 4] = hi1;
    }
}

// ---------------------------------------------------------------------------
// Kernel 2 (R6): reduce K-split partials, softmax/argmax, per-block me/cnt.
// ---------------------------------------------------------------------------
__global__ __launch_bounds__(256) void gate_kernel()
{
    __shared__ float Ls[64 * 65];
    __shared__ int   s_eid[64];
    const int b = blockIdx.x;        // 0..127
    const int t = threadIdx.x;
    const size_t off = (size_t)b * 64 * NEXP;

    #pragma unroll
    for (int i = 0; i < 4; i++) {
        const int idx4 = t + i * 256;     // 0..1023
        float4 v = *(const float4*)&g_part[off + (size_t)idx4 * 4];
        #pragma unroll
        for (int p = 1; p < KSPLIT; p++) {
            float4 w = *(const float4*)&g_part[(size_t)p * S_TOK * NEXP + off + (size_t)idx4 * 4];
            v.x += w.x; v.y += w.y; v.z += w.z; v.w += w.w;
        }
        const int r = (idx4 * 4) >> 6;
        const int e = (idx4 * 4) & 63;
        Ls[r * 65 + e + 0] = v.x;
        Ls[r * 65 + e + 1] = v.y;
        Ls[r * 65 + e + 2] = v.z;
        Ls[r * 65 + e + 3] = v.w;
    }
    __syncthreads();

    if (t < 64) {
        const int r = t;
        float m = -INFINITY; int am = 0;
        #pragma unroll 8
        for (int e = 0; e < NEXP; e++) {
            float v = Ls[r * 65 + e];
            if (v > m) { m = v; am = e; }
        }
        float sum = 0.f;
        #pragma unroll 8
        for (int e = 0; e < NEXP; e++) {
            float ex = expf(Ls[r * 65 + e] - m);
            Ls[r * 65 + e] = ex;
            sum += ex;
        }
        const float inv = 1.f / sum;
        #pragma unroll 8
        for (int e = 0; e < NEXP; e++) Ls[r * 65 + e] *= inv;
        const int s = b * 64 + r;
        g_eid[s]  = am;
        g_gate[s] = inv;
        s_eid[r]  = am;
    }
    __syncthreads();

    if (t < NEXP) {
        const int e = t;
        float msum = 0.f; int cnt = 0;
        #pragma unroll 8
        for (int r = 0; r < 64; r++) {
            msum += Ls[r * 65 + e];
            cnt  += (s_eid[r] == e);
        }
        g_me[b * NEXP + e]  = msum;
        g_cnt[b * NEXP + e] = cnt;
    }
}

// ---------------------------------------------------------------------------
// Kernel 3 (R9/R12 proven): scatter + exp_counts + l_aux.
// ---------------------------------------------------------------------------
__global__ __launch_bounds__(256) void scatter_kernel(float* __restrict__ out)
{
    __shared__ int   sc[NBLK64 * NEXP];   // 32 KB staged counts
    __shared__ int   s_part[4][64];
    __shared__ int   s_e[64];
    __shared__ float s_g[64];
    __shared__ int   cnt0[NEXP];
    __shared__ float s_val[NEXP];

    const int b = blockIdx.x;
    const int t = threadIdx.x;            // 0..255

    {
        const int4* g4 = (const int4*)g_cnt;
        int4* s4 = (int4*)sc;
        #pragma unroll
        for (int j = 0; j < 8; j++) s4[t + j * 256] = g4[t + j * 256];
    }
    if (t < 64) {
        s_e[t]  = g_eid[b * 64 + t];
        s_g[t]  = g_gate[b * 64 + t];
        cnt0[t] = 0;
    }
    __syncthreads();

    {
        const int tok = t & 63;
        const int q   = t >> 6;
        const int e   = s_e[tok];
        const int lo  = q * 32;
        const int hi  = (b < lo + 32) ? b : (lo + 32);
        int sum = 0;
        #pragma unroll 8
        for (int bp = lo; bp < hi; bp++) sum += sc[bp * NEXP + e];
        s_part[q][tok] = sum;
    }
    __syncthreads();

    int ee = 0, rank_w = 0, offs = 0; float gg = 0.f; unsigned mm = 0;
    if (t < 64) {
        ee   = s_e[t];
        gg   = s_g[t];
        offs = s_part[0][t] + s_part[1][t] + s_part[2][t] + s_part[3][t];
        mm   = __match_any_sync(0xFFFFFFFFu, ee);
        const int lane = t & 31;
        rank_w = __popc(mm & ((1u << lane) - 1u));
        if (t < 32 && lane == __ffs(mm) - 1) cnt0[ee] = __popc(mm);
    }
    __syncthreads();
    if (t >= 32 && t < 64) rank_w += cnt0[ee];
    if (t < 64) {
        const int rank = offs + rank_w;
        if (rank < CAP) {
            const int s = b * 64 + t;
            size_t base = (size_t)s * (NEXP * CAP) + (size_t)ee * CAP + rank;
            out[1 + base]       = gg;
            out[1 + SEC + base] = 1.0f;
        }
    }

    if (b == 0) {
        __syncthreads();
        {
            const int ex = t & 63;
            const int q  = t >> 6;
            int sum = 0;
            #pragma unroll 8
            for (int bp = q * 32; bp < q * 32 + 32; bp++) sum += sc[bp * NEXP + ex];
            s_part[q][ex] = sum;
        }
        __syncthreads();
        if (t < 64) {
            const int run = s_part[0][t] + s_part[1][t] + s_part[2][t] + s_part[3][t];
            float me_tot = 0.f;
            #pragma unroll 8
            for (int bp = 0; bp < NBLK64; bp++) me_tot += g_me[bp * NEXP + t];
            out[1 + 2 * SEC + t] = (float)run;
            s_val[t] = me_tot * (float)run;
        }
        __syncthreads();
        if (t == 0) {
            float acc = 0.f;
            for (int k = 0; k < NEXP; k++) acc += s_val[k];
            out[0] = acc * (1.f / 1048576.f);
        }
    }
}

// ---------------------------------------------------------------------------
extern "C" void kernel_launch(void* const* d_in, const int* in_sizes, int n_in,
                              void* d_out, int out_size)
{
    const float* x  = (const float*)d_in[0];
    const float* wg = (const float*)d_in[1];
    float* out = (float*)d_out;

    gemm_zero_kernel<<<GRID_G, THREADS>>>(x, wg, out);
    gate_kernel<<<NBLK64, 256>>>();
    scatter_kernel<<<NBLK64, 256>>>(out);
}

// round 17
// speedup vs baseline: 1.8694x; 1.3165x over previous
#include <cuda_runtime.h>
#include <cstdint>
#include <math.h>

// Problem constants
#define S_TOK 8192
#define MDIM  4096
#define NEXP  64
#define CAP   128
#define SEC   67108864ULL            // S*E*C
#define OUT_FLOATS 134217793ULL      // 1 + 2*SEC + 64
#define ZMAIN 134217728ULL           // floats zeroed by bulk path (512MB)

// GEMM tiling: R6 geometry halved -> 2 CTAs per SM
#define TILE_M 128                   // tokens per CTA
#define KB     16
#define KSPLIT 4
#define KCHUNK (MDIM / KSPLIT)       // 1024
#define NSTEP  (KCHUNK / KB)         // 64
#define NTB    (S_TOK / TILE_M)      // 64 token blocks
#define GRID_G (NTB * KSPLIT)        // 256 CTAs (2 per SM)
#define CTHR   128                   // compute threads (4 warps)
#define THREADS (CTHR + 32)          // + 1 TMA-zero warp = 160
#define LDA 132                      // A smem row stride (floats)
#define LDB 68                       // B smem row stride (floats)

#define ZCHUNK 4096                  // bytes per bulk store
#define ZPC    512                   // chunks per CTA (256*512*4KB = 512MB)

#define NBLK64 (S_TOK / 64)          // 128 blocks for gate/scatter

typedef unsigned long long u64;
typedef unsigned int u32;

// ---------- scratch (device globals; fully overwritten each launch) ----------
__device__ float g_part[KSPLIT * S_TOK * NEXP];   // 8 MB partial logits
__device__ int   g_eid[S_TOK];
__device__ float g_gate[S_TOK];
__device__ float g_me[NBLK64 * NEXP];
__device__ int   g_cnt[NBLK64 * NEXP];

// packed f32x2 FMA (PTX-only; ptxas never auto-fuses)
__device__ __forceinline__ void ffma2(u64& d, u64 a, u64 b) {
    asm("fma.rn.f32x2 %0, %1, %2, %0;" : "+l"(d) : "l"(a), "l"(b));
}
__device__ __forceinline__ u64 dup2(float b) {
    u64 r; unsigned u = __float_as_uint(b);
    asm("mov.b64 %0, {%1, %1};" : "=l"(r) : "r"(u));
    return r;
}
__device__ __forceinline__ void barc() {   // compute-warps-only barrier
    asm volatile("bar.sync 1, %0;" :: "n"(CTHR) : "memory");
}
__device__ __forceinline__ u32 smem_u32(const void* p) {
    u32 a;
    asm("{ .reg .u64 t; cvta.to.shared.u64 t, %1; cvt.u32.u64 %0, t; }"
        : "=r"(a) : "l"(p));
    return a;
}

// ---------------------------------------------------------------------------
// Kernel 1: 128x64 fp32 GEMM over a K/4 chunk, R6 inner loop verbatim
// (per-thread 8 tok x 8 exp, 32 FFMA2 / 4 LDS.128 / 8 dup2 per kk, double
// buffer, one barrier/step) but 4 compute warps per CTA and 2 CTAs per SM
// so cross-CTA interleaving hides the barrier shadow.
// Warp 4 = TMA bulk-zero of 2MB of the output (R9 distributed engine).
// ---------------------------------------------------------------------------
__global__ __launch_bounds__(THREADS, 2) void gemm_zero_kernel(
    const float* __restrict__ x, const float* __restrict__ wg,
    float* __restrict__ out)
{
    __shared__ float sA[2][KB * LDA];                 // 2 x 8.25 KB
    __shared__ float sB[2][KB * LDB];                 // 2 x 4.25 KB
    __shared__ alignas(16) float4 zbuf[ZCHUNK / 16];  // 4 KB zeros

    const int t  = threadIdx.x;
    const int bx = blockIdx.x;

    {
        const float4 z = make_float4(0.f, 0.f, 0.f, 0.f);
        for (int i = t; i < ZCHUNK / 16; i += THREADS) zbuf[i] = z;
    }
    __syncthreads();

    if (t >= CTHR) {
        // ---------------- TMA zero warp ----------------
        const int zt = t - CTHR;
        if (zt == 0) {
            asm volatile("fence.proxy.async.shared::cta;" ::: "memory");
            const u32 zaddr = smem_u32(zbuf);
            char* dst = (char*)out + (size_t)bx * (ZPC * (size_t)ZCHUNK);
            #pragma unroll 4
            for (int c = 0; c < ZPC; c++) {
                asm volatile(
                    "cp.async.bulk.global.shared::cta.bulk_group [%0], [%1], %2;"
                    :: "l"(dst + (size_t)c * ZCHUNK), "r"(zaddr), "r"(ZCHUNK)
                    : "memory");
            }
            asm volatile("cp.async.bulk.commit_group;" ::: "memory");
            asm volatile("cp.async.bulk.wait_group 0;" ::: "memory");
        }
        if (bx == 0) {   // tail: last 65 floats
            for (int i = zt; i < (int)(OUT_FLOATS - ZMAIN); i += 32)
                out[ZMAIN + i] = 0.0f;
        }
        return;
    }

    // ---------------- compute warps (R6 geometry, halved) ----------------
    const int tb = bx & (NTB - 1);     // token block (0..63)
    const int kh = bx >> 6;            // k chunk (0..3)
    const int w    = t >> 5;           // warp 0..3
    const int lane = t & 31;
    const int tb2  = w >> 1;           // warp token sub-block (0..1): 64 tokens
    const int eb   = w & 1;            // warp expert half (0..1): 32 experts
    const int tg   = lane >> 2;        // token group (0..7): 8 tokens
    const int eg   = lane & 3;         // expert group (0..3): 8 experts
    const int tok0 = tb2 * 64 + tg * 8;
    const int e0   = eb * 32 + eg * 8;

    u64 acc[4][8];                     // 4 token-pairs x 8 experts
    #pragma unroll
    for (int p = 0; p < 4; p++)
        #pragma unroll
        for (int j = 0; j < 8; j++) acc[p][j] = 0ULL;

    const float* xblk = x  + (size_t)tb * TILE_M * MDIM + (size_t)kh * KCHUNK;
    const float* wblk = wg + (size_t)kh * KCHUNK;

    // staging: A = 4 float4/thread (rows arow+i*32, col quad akq)
    //          B = 2 float4/thread (rows t>>1 via idx, col quads)
    const int arow = t >> 2;           // 0..31
    const int akq  = t & 3;            // 0..3
    const int br0  = (t * 2) >> 2;     // B row of first float4 (0..63)
    const int bq0  = (t * 2) & 3;      // quad of first float4
    const int br1  = (t * 2 + 1) >> 2;
    const int bq1  = (t * 2 + 1) & 3;

    float4 pa[4]; float4 pb0, pb1;
    #pragma unroll
    for (int i = 0; i < 4; i++)
        pa[i] = *(const float4*)(xblk + (size_t)(arow + i * 32) * MDIM + akq * 4);
    pb0 = *(const float4*)(wblk + (size_t)br0 * MDIM + bq0 * 4);
    pb1 = *(const float4*)(wblk + (size_t)br1 * MDIM + bq1 * 4);

    // stage step 0
    #pragma unroll
    for (int i = 0; i < 4; i++) {
        const int r = arow + i * 32;
        sA[0][(akq * 4 + 0) * LDA + r] = pa[i].x;
        sA[0][(akq * 4 + 1) * LDA + r] = pa[i].y;
        sA[0][(akq * 4 + 2) * LDA + r] = pa[i].z;
        sA[0][(akq * 4 + 3) * LDA + r] = pa[i].w;
    }
    sB[0][(bq0 * 4 + 0) * LDB + br0] = pb0.x;
    sB[0][(bq0 * 4 + 1) * LDB + br0] = pb0.y;
    sB[0][(bq0 * 4 + 2) * LDB + br0] = pb0.z;
    sB[0][(bq0 * 4 + 3) * LDB + br0] = pb0.w;
    sB[0][(bq1 * 4 + 0) * LDB + br1] = pb1.x;
    sB[0][(bq1 * 4 + 1) * LDB + br1] = pb1.y;
    sB[0][(bq1 * 4 + 2) * LDB + br1] = pb1.z;
    sB[0][(bq1 * 4 + 3) * LDB + br1] = pb1.w;
    barc();

    #pragma unroll 1
    for (int s = 0; s < NSTEP; s++) {
        const int cur = s & 1;

        if (s + 1 < NSTEP) {           // prefetch next step
            const int k1 = (s + 1) * KB;
            #pragma unroll
            for (int i = 0; i < 4; i++)
                pa[i] = *(const float4*)(xblk + (size_t)(arow + i * 32) * MDIM + k1 + akq * 4);
            pb0 = *(const float4*)(wblk + (size_t)br0 * MDIM + k1 + bq0 * 4);
            pb1 = *(const float4*)(wblk + (size_t)br1 * MDIM + k1 + bq1 * 4);
        }

        // R6 inner loop: 4 LDS.128 + 8 dup2 + 32 FFMA2 per kk
        #pragma unroll
        for (int kk = 0; kk < KB; kk++) {
            const float* ap = &sA[cur][kk * LDA + tok0];
            ulonglong2 a01 = *(const ulonglong2*)(ap);
            ulonglong2 a23 = *(const ulonglong2*)(ap + 4);
            float4 b03 = *(const float4*)&sB[cur][kk * LDB + e0];
            float4 b47 = *(const float4*)&sB[cur][kk * LDB + e0 + 4];
            u64 ar[4] = { a01.x, a01.y, a23.x, a23.y };
            u64 bd[8] = { dup2(b03.x), dup2(b03.y), dup2(b03.z), dup2(b03.w),
                          dup2(b47.x), dup2(b47.y), dup2(b47.z), dup2(b47.w) };
            #pragma unroll
            for (int p = 0; p < 4; p++)
                #pragma unroll
                for (int j = 0; j < 8; j++)
                    ffma2(acc[p][j], ar[p], bd[j]);
        }

        if (s + 1 < NSTEP) {           // stage next step into other buffer
            const int nxt = cur ^ 1;
            #pragma unroll
            for (int i = 0; i < 4; i++) {
                const int r = arow + i * 32;
                sA[nxt][(akq * 4 + 0) * LDA + r] = pa[i].x;
                sA[nxt][(akq * 4 + 1) * LDA + r] = pa[i].y;
                sA[nxt][(akq * 4 + 2) * LDA + r] = pa[i].z;
                sA[nxt][(akq * 4 + 3) * LDA + r] = pa[i].w;
            }
            sB[nxt][(bq0 * 4 + 0) * LDB + br0] = pb0.x;
            sB[nxt][(bq0 * 4 + 1) * LDB + br0] = pb0.y;
            sB[nxt][(bq0 * 4 + 2) * LDB + br0] = pb0.z;
            sB[nxt][(bq0 * 4 + 3) * LDB + br0] = pb0.w;
            sB[nxt][(bq1 * 4 + 0) * LDB + br1] = pb1.x;
            sB[nxt][(bq1 * 4 + 1) * LDB + br1] = pb1.y;
            sB[nxt][(bq1 * 4 + 2) * LDB + br1] = pb1.z;
            sB[nxt][(bq1 * 4 + 3) * LDB + br1] = pb1.w;
        }
        barc();
    }

    // epilogue: write partial logits [kh][token][expert]
    float* part = g_part + (size_t)kh * S_TOK * NEXP;
    #pragma unroll
    for (int p = 0; p < 4; p++) {
        const size_t t0 = (size_t)tb * TILE_M + tok0 + p * 2;
        float4 lo0, lo1, hi0, hi1;
        lo0.x = __uint_as_float((unsigned)acc[p][0]);
        lo0.y = __uint_as_float((unsigned)acc[p][1]);
        lo0.z = __uint_as_float((unsigned)acc[p][2]);
        lo0.w = __uint_as_float((unsigned)acc[p][3]);
        lo1.x = __uint_as_float((unsigned)acc[p][4]);
        lo1.y = __uint_as_float((unsigned)acc[p][5]);
        lo1.z = __uint_as_float((unsigned)acc[p][6]);
        lo1.w = __uint_as_float((unsigned)acc[p][7]);
        hi0.x = __uint_as_float((unsigned)(acc[p][0] >> 32));
        hi0.y = __uint_as_float((unsigned)(acc[p][1] >> 32));
        hi0.z = __uint_as_float((unsigned)(acc[p][2] >> 32));
        hi0.w = __uint_as_float((unsigned)(acc[p][3] >> 32));
        hi1.x = __uint_as_float((unsigned)(acc[p][4] >> 32));
        hi1.y = __uint_as_float((unsigned)(acc[p][5] >> 32));
        hi1.z = __uint_as_float((unsigned)(acc[p][6] >> 32));
        hi1.w = __uint_as_float((unsigned)(acc[p][7] >> 32));
        *(float4*)&part[t0 * NEXP + e0 + 0]       = lo0;
        *(float4*)&part[t0 * NEXP + e0 + 4]       = lo1;
        *(float4*)&part[(t0 + 1) * NEXP + e0 + 0] = hi0;
        *(float4*)&part[(t0 + 1) * NEXP + e0 + 4] = hi1;
    }
}

// ---------------------------------------------------------------------------
// Kernel 2 (R6): reduce K-split partials, softmax/argmax, per-block me/cnt.
// ---------------------------------------------------------------------------
__global__ __launch_bounds__(256) void gate_kernel()
{
    __shared__ float Ls[64 * 65];
    __shared__ int   s_eid[64];
    const int b = blockIdx.x;        // 0..127
    const int t = threadIdx.x;
    const size_t off = (size_t)b * 64 * NEXP;

    #pragma unroll
    for (int i = 0; i < 4; i++) {
        const int idx4 = t + i * 256;     // 0..1023
        float4 v = *(const float4*)&g_part[off + (size_t)idx4 * 4];
        #pragma unroll
        for (int p = 1; p < KSPLIT; p++) {
            float4 w = *(const float4*)&g_part[(size_t)p * S_TOK * NEXP + off + (size_t)idx4 * 4];
            v.x += w.x; v.y += w.y; v.z += w.z; v.w += w.w;
        }
        const int r = (idx4 * 4) >> 6;
        const int e = (idx4 * 4) & 63;
        Ls[r * 65 + e + 0] = v.x;
        Ls[r * 65 + e + 1] = v.y;
        Ls[r * 65 + e + 2] = v.z;
        Ls[r * 65 + e + 3] = v.w;
    }
    __syncthreads();

    if (t < 64) {
        const int r = t;
        float m = -INFINITY; int am = 0;
        #pragma unroll 8
        for (int e = 0; e < NEXP; e++) {
            float v = Ls[r * 65 + e];
            if (v > m) { m = v; am = e; }
        }
        float sum = 0.f;
        #pragma unroll 8
        for (int e = 0; e < NEXP; e++) {
            float ex = expf(Ls[r * 65 + e] - m);
            Ls[r * 65 + e] = ex;
            sum += ex;
        }
        const float inv = 1.f / sum;
        #pragma unroll 8
        for (int e = 0; e < NEXP; e++) Ls[r * 65 + e] *= inv;
        const int s = b * 64 + r;
        g_eid[s]  = am;
        g_gate[s] = inv;
        s_eid[r]  = am;
    }
    __syncthreads();

    if (t < NEXP) {
        const int e = t;
        float msum = 0.f; int cnt = 0;
        #pragma unroll 8
        for (int r = 0; r < 64; r++) {
            msum += Ls[r * 65 + e];
            cnt  += (s_eid[r] == e);
        }
        g_me[b * NEXP + e]  = msum;
        g_cnt[b * NEXP + e] = cnt;
    }
}

// ---------------------------------------------------------------------------
// Kernel 3 (R9/R12 proven): scatter + exp_counts + l_aux.
// ---------------------------------------------------------------------------
__global__ __launch_bounds__(256) void scatter_kernel(float* __restrict__ out)
{
    __shared__ int   sc[NBLK64 * NEXP];   // 32 KB staged counts
    __shared__ int   s_part[4][64];
    __shared__ int   s_e[64];
    __shared__ float s_g[64];
    __shared__ int   cnt0[NEXP];
    __shared__ float s_val[NEXP];

    const int b = blockIdx.x;
    const int t = threadIdx.x;            // 0..255

    {
        const int4* g4 = (const int4*)g_cnt;
        int4* s4 = (int4*)sc;
        #pragma unroll
        for (int j = 0; j < 8; j++) s4[t + j * 256] = g4[t + j * 256];
    }
    if (t < 64) {
        s_e[t]  = g_eid[b * 64 + t];
        s_g[t]  = g_gate[b * 64 + t];
        cnt0[t] = 0;
    }
    __syncthreads();

    {
        const int tok = t & 63;
        const int q   = t >> 6;
        const int e   = s_e[tok];
        const int lo  = q * 32;
        const int hi  = (b < lo + 32) ? b : (lo + 32);
        int sum = 0;
        #pragma unroll 8
        for (int bp = lo; bp < hi; bp++) sum += sc[bp * NEXP + e];
        s_part[q][tok] = sum;
    }
    __syncthreads();

    int ee = 0, rank_w = 0, offs = 0; float gg = 0.f; unsigned mm = 0;
    if (t < 64) {
        ee   = s_e[t];
        gg   = s_g[t];
        offs = s_part[0][t] + s_part[1][t] + s_part[2][t] + s_part[3][t];
        mm   = __match_any_sync(0xFFFFFFFFu, ee);
        const int lane = t & 31;
        rank_w = __popc(mm & ((1u << lane) - 1u));
        if (t < 32 && lane == __ffs(mm) - 1) cnt0[ee] = __popc(mm);
    }
    __syncthreads();
    if (t >= 32 && t < 64) rank_w += cnt0[ee];
    if (t < 64) {
        const int rank = offs + rank_w;
        if (rank < CAP) {
            const int s = b * 64 + t;
            size_t base = (size_t)s * (NEXP * CAP) + (size_t)ee * CAP + rank;
            out[1 + base]       = gg;
            out[1 + SEC + base] = 1.0f;
        }
    }

    if (b == 0) {
        __syncthreads();
        {
            const int ex = t & 63;
            const int q  = t >> 6;
            int sum = 0;
            #pragma unroll 8
            for (int bp = q * 32; bp < q * 32 + 32; bp++) sum += sc[bp * NEXP + ex];
            s_part[q][ex] = sum;
        }
        __syncthreads();
        if (t < 64) {
            const int run = s_part[0][t] + s_part[1][t] + s_part[2][t] + s_part[3][t];
            float me_tot = 0.f;
            #pragma unroll 8
            for (int bp = 0; bp < NBLK64; bp++) me_tot += g_me[bp * NEXP + t];
            out[1 + 2 * SEC + t] = (float)run;
            s_val[t] = me_tot * (float)run;
        }
        __syncthreads();
        if (t == 0) {
            float acc = 0.f;
            for (int k = 0; k < NEXP; k++) acc += s_val[k];
            out[0] = acc * (1.f / 1048576.f);
        }
    }
}

// ---------------------------------------------------------------------------
extern "C" void kernel_launch(void* const* d_in, const int* in_sizes, int n_in,
                              void* d_out, int out_size)
{
    const float* x  = (const float*)d_in[0];
    const float* wg = (const float*)d_in[1];
    float* out = (float*)d_out;

    gemm_zero_kernel<<<GRID_G, THREADS>>>(x, wg, out);
    gate_kernel<<<NBLK64, 256>>>();
    scatter_kernel<<<NBLK64, 256>>>(out);
}